// round 6
// baseline (speedup 1.0000x reference)
#include <cuda_runtime.h>
#include <math.h>

// ---------------------------------------------------------------------------
// GemoLoss — GB300 implementation
// Shapes fixed by the problem: n=4, h=768, w=1024, S=131072
// ---------------------------------------------------------------------------

#define NIMG 4
#define H    768
#define W    1024
#define P    (H * W)          // 786432
#define S    131072
#define NB   (P / 1024)       // 768 blocks of 1024 pixels per image

#define MASK_VALUE (-1e-8f)

// -------------------- device scratch (no allocations allowed) ---------------
__device__ float    g_edge [NIMG * P];
__device__ float    g_theta[NIMG * P];
__device__ int      g_esel [NIMG * P];   // stable select array for edge mask
__device__ int      g_vsel [NIMG * P];   // stable select array for valid mask
__device__ unsigned g_emax_bits[NIMG];   // edge max as float bits (edge >= 0)
__device__ int      g_eblk[NIMG * NB];   // block counts -> exclusive prefixes
__device__ int      g_vblk[NIMG * NB];
__device__ int      g_ecount[NIMG];
__device__ int      g_vcount[NIMG];
__device__ double   g_acc_eq;
__device__ double   g_acc_uq;

// ----------------------------------------------------------------------------
__global__ void k_init() {
    int t = threadIdx.x;
    if (t < NIMG) g_emax_bits[t] = 0u;
    if (t == 0) { g_acc_eq = 0.0; g_acc_uq = 0.0; }
}

// ----------------------------------------------------------------------------
// Sobel on channel 0 of images (n,3,h,w). Cross-correlation (lax.conv does not
// flip kernels). Border pixels (pad) get edge=0, theta=0. Fused per-image max.
__global__ void k_sobel(const float* __restrict__ images) {
    int gid = blockIdx.x * blockDim.x + threadIdx.x;   // < NIMG*P, P%256==0
    int img = gid / P;
    int p   = gid - img * P;
    int y = p / W;
    int x = p - y * W;

    float e = 0.0f, th = 0.0f;
    if (y > 0 && y < H - 1 && x > 0 && x < W - 1) {
        const float* I = images + (size_t)img * 3 * P;
        float a  = I[(y - 1) * W + (x - 1)];
        float b  = I[(y - 1) * W + (x    )];
        float c  = I[(y - 1) * W + (x + 1)];
        float d  = I[(y    ) * W + (x - 1)];
        float f  = I[(y    ) * W + (x + 1)];
        float g  = I[(y + 1) * W + (x - 1)];
        float hh = I[(y + 1) * W + (x    )];
        float i  = I[(y + 1) * W + (x + 1)];

        // kx = [[-1,0,1],[-2,0,2],[-1,0,1]], ky = [[1,2,1],[0,0,0],[-1,-2,-1]]
        float gx = -a;  gx += c;  gx += -2.0f * d;  gx += 2.0f * f;  gx += -g;  gx += i;
        float gy =  a;  gy += 2.0f * b;  gy += c;  gy += -g;  gy += -2.0f * hh; gy += -i;

        e  = sqrtf(gx * gx + gy * gy);
        th = atan2f(gy, gx);
    }
    g_edge [gid] = e;
    g_theta[gid] = th;

    // block max -> atomicMax (uint order == float order for non-negative)
    __shared__ float smax[8];                 // 256 threads = 8 warps
    int lane = threadIdx.x & 31, wid = threadIdx.x >> 5;
    float m = e;
    #pragma unroll
    for (int off = 16; off; off >>= 1)
        m = fmaxf(m, __shfl_down_sync(0xffffffffu, m, off));
    if (lane == 0) smax[wid] = m;
    __syncthreads();
    if (wid == 0) {
        m = (lane < 8) ? smax[lane] : 0.0f;
        #pragma unroll
        for (int off = 4; off; off >>= 1)
            m = fmaxf(m, __shfl_down_sync(0xffffffffu, m, off));
        if (lane == 0) atomicMax(&g_emax_bits[img], __float_as_uint(m));
    }
}

// ----------------------------------------------------------------------------
// Per-block counts of the two boolean masks.
__global__ void k_count(const float* __restrict__ tgt) {
    int img = blockIdx.x / NB;
    int b   = blockIdx.x - img * NB;
    int p   = b * 1024 + threadIdx.x;

    float thresh = 0.1f * __uint_as_float(g_emax_bits[img]);
    int e = (g_edge[(size_t)img * P + p] >= thresh) ? 1 : 0;
    int v = (tgt[(size_t)img * P + p] > MASK_VALUE) ? 1 : 0;

    int ec = __syncthreads_count(e);
    int vc = __syncthreads_count(v);
    if (threadIdx.x == 0) {
        g_eblk[img * NB + b] = ec;
        g_vblk[img * NB + b] = vc;
    }
}

// ----------------------------------------------------------------------------
// One block per image: inclusive scan of NB block counts -> exclusive offsets.
__global__ void k_scan() {
    int img = blockIdx.x;
    int t   = threadIdx.x;          // blockDim = 1024 >= NB
    __shared__ int sh[1024];

    // ---- edge counts ----
    int c = (t < NB) ? g_eblk[img * NB + t] : 0;
    sh[t] = c;
    for (int off = 1; off < 1024; off <<= 1) {
        __syncthreads();
        int v = (t >= off) ? sh[t - off] : 0;
        __syncthreads();
        sh[t] += v;
    }
    __syncthreads();
    if (t < NB) g_eblk[img * NB + t] = sh[t] - c;   // exclusive
    if (t == NB - 1) g_ecount[img] = sh[t];
    __syncthreads();

    // ---- valid counts ----
    int cv = (t < NB) ? g_vblk[img * NB + t] : 0;
    sh[t] = cv;
    for (int off = 1; off < 1024; off <<= 1) {
        __syncthreads();
        int v = (t >= off) ? sh[t - off] : 0;
        __syncthreads();
        sh[t] += v;
    }
    __syncthreads();
    if (t < NB) g_vblk[img * NB + t] = sh[t] - cv;
    if (t == NB - 1) g_vcount[img] = sh[t];
}

// ----------------------------------------------------------------------------
// Intra-block exclusive prefix of a 0/1 flag (1024 threads).
__device__ __forceinline__ int block_excl_prefix(int flag, int* wsum, int tid) {
    unsigned bal = __ballot_sync(0xffffffffu, flag != 0);
    int lane = tid & 31, wid = tid >> 5;
    int lpre = __popc(bal & ((1u << lane) - 1u));
    if (lane == 0) wsum[wid] = __popc(bal);
    __syncthreads();
    if (wid == 0) {
        int v = wsum[lane];                 // 32 warps exactly
        #pragma unroll
        for (int off = 1; off < 32; off <<= 1) {
            int tmp = __shfl_up_sync(0xffffffffu, v, off);
            if (lane >= off) v += tmp;
        }
        wsum[lane] = v;                     // inclusive
    }
    __syncthreads();
    int base = (wid == 0) ? 0 : wsum[wid - 1];
    return base + lpre;
}

// ----------------------------------------------------------------------------
// Stable scatter of true-pixel indices (== argsort(!mask) prefix).
__global__ void k_scatter(const float* __restrict__ tgt) {
    int img = blockIdx.x / NB;
    int b   = blockIdx.x - img * NB;
    int tid = threadIdx.x;
    int p   = b * 1024 + tid;

    float thresh = 0.1f * __uint_as_float(g_emax_bits[img]);
    int e = (g_edge[(size_t)img * P + p] >= thresh) ? 1 : 0;
    int v = (tgt[(size_t)img * P + p] > MASK_VALUE) ? 1 : 0;

    __shared__ int wse[32];
    __shared__ int wsv[32];
    int re = block_excl_prefix(e, wse, tid);
    __syncthreads();
    int rv = block_excl_prefix(v, wsv, tid);

    if (e) g_esel[(size_t)img * P + g_eblk[img * NB + b] + re] = p;
    if (v) g_vsel[(size_t)img * P + g_vblk[img * NB + b] + rv] = p;
}

// ----------------------------------------------------------------------------
// Main sampling kernel: one thread per (img, s). 4 pairs each.
__global__ void k_sample(const float* __restrict__ inp,
                         const float* __restrict__ tgt,
                         const int*   __restrict__ ra,
                         const int*   __restrict__ rd,
                         const int*   __restrict__ rp) {
    int gid = blockIdx.x * blockDim.x + threadIdx.x;
    double eq = 0.0, uq = 0.0;

    if (gid < NIMG * S) {
        int img = gid / S;
        int s   = gid - img * S;
        const float* in_i = inp + (size_t)img * P;
        const float* tg_i = tgt + (size_t)img * P;

        int ec = g_ecount[img];
        int vc = g_vcount[img];

        // anchor = edge_idx[ra % minlen]; if no edge pixels, argsort -> identity -> pixel 0
        int anchor;
        if (ec > 0) anchor = g_esel[(size_t)img * P + (ra[gid] % ec)];
        else        anchor = 0;

        float th = g_theta[(size_t)img * P + anchor];
        float ct = cosf(th), st = sinf(th);
        int row_a = anchor / W;
        int col_a = anchor - row_a * W;

        int pix[4];
        #pragma unroll
        for (int j = 0; j < 4; j++) {
            int   rdv  = rd[((size_t)img * 4 + j) * S + s];
            float sign = (j < 2) ? -1.0f : 1.0f;
            float d    = ((float)rdv + 2.0f) * sign;
            int cc = col_a + (int)rintf(d * ct);   // jnp.round = half-to-even
            int rr = row_a + (int)rintf(d * st);
            cc = min(max(cc, 0), W - 1);
            rr = min(max(rr, 0), H - 1);
            pix[j] = rr * W + cc;
        }

        int rA, rB;
        if (vc > 0) {
            int s0 = rp[(size_t)img * 2 * S + 2 * s    ] % vc;
            int s1 = rp[(size_t)img * 2 * S + 2 * s + 1] % vc;
            rA = g_vsel[(size_t)img * P + s0];
            rB = g_vsel[(size_t)img * P + s1];
        } else {
            rA = 0; rB = 0;   // vidx -> identity, sh = rp % 1 = 0
        }

        int A[4] = { pix[0], pix[1], pix[2], rA };
        int B[4] = { pix[1], pix[2], pix[3], rB };

        const float hi = 1.0f + 0.03f;             // 1 + SIGMA in f32
        const float lo = (float)(1.0 / 1.03);      // computed in double like Python

        #pragma unroll
        for (int k = 0; k < 4; k++) {
            float iA = __ldg(in_i + A[k]);
            float iB = __ldg(in_i + B[k]);
            float tA = __ldg(tg_i + A[k]);
            float tB = __ldg(tg_i + B[k]);

            float cm = ((tA > MASK_VALUE) && (tB > MASK_VALUE)) ? 1.0f : 0.0f;
            float ratio = (tA + 1e-6f) / (tB + 1e-6f);
            bool  meq = (ratio < hi) && (ratio > lo);

            if (meq) {
                float dd = iA - iB;
                eq += (double)(dd * dd * cm);
            } else {
                float lbl = (ratio >= hi) ? 1.0f : -1.0f;
                uq += (double)(log1pf(expf((iB - iA) * lbl)) * cm);
            }
        }
    }

    // block reduce (doubles) -> single atomicAdd pair per block
    #pragma unroll
    for (int off = 16; off; off >>= 1) {
        eq += __shfl_down_sync(0xffffffffu, eq, off);
        uq += __shfl_down_sync(0xffffffffu, uq, off);
    }
    __shared__ double sh_eq[8];
    __shared__ double sh_uq[8];
    int lane = threadIdx.x & 31, wid = threadIdx.x >> 5;
    if (lane == 0) { sh_eq[wid] = eq; sh_uq[wid] = uq; }
    __syncthreads();
    if (wid == 0) {
        eq = (lane < 8) ? sh_eq[lane] : 0.0;
        uq = (lane < 8) ? sh_uq[lane] : 0.0;
        #pragma unroll
        for (int off = 4; off; off >>= 1) {
            eq += __shfl_down_sync(0xffffffffu, eq, off);
            uq += __shfl_down_sync(0xffffffffu, uq, off);
        }
        if (lane == 0) {
            atomicAdd(&g_acc_eq, eq);
            atomicAdd(&g_acc_uq, uq);
        }
    }
}

// ----------------------------------------------------------------------------
__global__ void k_final(float* __restrict__ out) {
    const double ALPHA = 1.0;
    double denom = 4.0 * (double)S;                       // pairs per image
    double loss  = (ALPHA * g_acc_eq + g_acc_uq) / denom / (double)NIMG;
    out[0] = (float)loss;
}

// ----------------------------------------------------------------------------
extern "C" void kernel_launch(void* const* d_in, const int* in_sizes, int n_in,
                              void* d_out, int out_size) {
    (void)in_sizes; (void)n_in; (void)out_size;

    const float* inputs  = (const float*)d_in[0];
    const float* targets = (const float*)d_in[1];
    const float* images  = (const float*)d_in[2];
    const int*   ra      = (const int*)d_in[3];
    const int*   rd      = (const int*)d_in[4];
    const int*   rp      = (const int*)d_in[5];
    float*       out     = (float*)d_out;

    k_init   <<<1, 32>>>();
    k_sobel  <<<(NIMG * P) / 256, 256>>>(images);
    k_count  <<<NIMG * NB, 1024>>>(targets);
    k_scan   <<<NIMG, 1024>>>();
    k_scatter<<<NIMG * NB, 1024>>>(targets);
    k_sample <<<(NIMG * S + 255) / 256, 256>>>(inputs, targets, ra, rd, rp);
    k_final  <<<1, 1>>>(out);
}